// round 5
// baseline (speedup 1.0000x reference)
#include <cuda_runtime.h>
#include <cstdint>

// ============================================================================
// Problem constants
// ============================================================================
static constexpr int M_TOK = 8192;
static constexpr int N_OUT = 4096;
static constexpr int K_IN  = 4096;
static constexpr long long MN = (long long)M_TOK * N_OUT;   // 33554432

// GEMM tiling (baseline-PTX path: mma.sync m16n8k32 s8 + cp.async + ldmatrix)
static constexpr int BM = 128;
static constexpr int BN = 256;
static constexpr int BK = 64;                // bytes of K per stage (int8)
static constexpr int NKT = K_IN / BK;        // 64 iterations
static constexpr int STAGES = 4;

static constexpr int A_TILE = BM * BK;       // 8192 B
static constexpr int B_TILE = BN * BK;       // 16384 B
static constexpr int STAGE_BYTES = A_TILE + B_TILE;       // 24576 B
static constexpr int SMEM_TOTAL  = STAGES * STAGE_BYTES;  // 98304 B

// Packed int8 operand scratch (__device__ globals: allowed, no allocation)
__device__ __align__(1024) int8_t g_xq[(size_t)M_TOK * K_IN];   // 32 MB
__device__ __align__(1024) int8_t g_wq[(size_t)N_OUT * K_IN];   // 16 MB

// ============================================================================
// PTX helpers (ALL baseline-PTX — nothing 'sm_103a'-gated)
// ============================================================================
__device__ __forceinline__ uint32_t smem_u32(const void* p) {
    uint32_t a;
    asm("{ .reg .u64 t; cvta.to.shared.u64 t, %1; cvt.u32.u64 %0, t; }"
        : "=r"(a) : "l"(p));
    return a;
}

#define CP_ASYNC16(sdst, gsrc) \
    asm volatile("cp.async.cg.shared.global [%0], [%1], 16;" \
                 :: "r"(sdst), "l"(gsrc) : "memory")
#define CP_COMMIT() asm volatile("cp.async.commit_group;" ::: "memory")
#define CP_WAIT(n)  asm volatile("cp.async.wait_group %0;" :: "n"(n) : "memory")

// Swizzled byte offset inside a [rows][64B] tile: 4 chunks of 16B per row,
// chunk ^= (row>>1)&3  ->  8 consecutive rows hit 8 distinct bank-chunks.
__device__ __forceinline__ uint32_t swz64(int row, int ch) {
    return (uint32_t)(row * 64 + ((ch ^ ((row >> 1) & 3)) << 4));
}

__device__ __forceinline__ void ldmatrix_x4(uint32_t& r0, uint32_t& r1,
                                            uint32_t& r2, uint32_t& r3,
                                            uint32_t addr) {
    asm volatile("ldmatrix.sync.aligned.m8n8.x4.shared.b16 {%0,%1,%2,%3}, [%4];"
                 : "=r"(r0), "=r"(r1), "=r"(r2), "=r"(r3) : "r"(addr));
}

__device__ __forceinline__ void mma_s8(int* c, const uint32_t* a, const uint32_t* b) {
    asm volatile(
        "mma.sync.aligned.m16n8k32.row.col.s32.s8.s8.s32 "
        "{%0,%1,%2,%3}, {%4,%5,%6,%7}, {%8,%9}, {%0,%1,%2,%3};"
        : "+r"(c[0]), "+r"(c[1]), "+r"(c[2]), "+r"(c[3])
        : "r"(a[0]), "r"(a[1]), "r"(a[2]), "r"(a[3]), "r"(b[0]), "r"(b[1]));
}

// ============================================================================
// Kernel 1: int32 carriers -> packed int8 scratch
// ============================================================================
static constexpr size_t XT = ((size_t)M_TOK * K_IN) / 16;   // 2097152
static constexpr size_t WT = ((size_t)N_OUT * K_IN) / 16;   // 1048576

__device__ __forceinline__ uint32_t pack4(int4 v) {
    return ((uint32_t)v.x & 0xFFu) | (((uint32_t)v.y & 0xFFu) << 8) |
           (((uint32_t)v.z & 0xFFu) << 16) | ((uint32_t)v.w << 24);
}

__global__ __launch_bounds__(256) void pack_kernel(const int* __restrict__ x,
                                                   const int* __restrict__ w) {
    size_t t = (size_t)blockIdx.x * 256 + threadIdx.x;
    const int4* src;
    int8_t* dst;
    if (t < XT) {
        src = reinterpret_cast<const int4*>(x) + t * 4;
        dst = g_xq + t * 16;
    } else {
        size_t u = t - XT;
        src = reinterpret_cast<const int4*>(w) + u * 4;
        dst = g_wq + u * 16;
    }
    int4 a = src[0], b = src[1], c = src[2], d = src[3];
    *reinterpret_cast<uint4*>(dst) =
        make_uint4(pack4(a), pack4(b), pack4(c), pack4(d));
}

// ============================================================================
// Kernel 2: multistage cp.async + ldmatrix + IMMA (mma.sync s8) GEMM
//   256 threads, 8 warps, warp tile 64x64, CTA tile 128x256, BK=64.
// ============================================================================
template <bool FOUT>
__global__ __launch_bounds__(256, 1)
void gemm_i8_kernel(const float* __restrict__ scale_ptr, void* __restrict__ outv) {
    extern __shared__ char smem[];
    const uint32_t sb = smem_u32(smem);
    const int tid  = threadIdx.x;
    const int wid  = tid >> 5;
    const int lane = tid & 31;

    const int m0 = blockIdx.y * BM;
    const int n0 = blockIdx.x * BN;

    const int8_t* gA = g_xq + (size_t)m0 * K_IN;
    const int8_t* gB = g_wq + (size_t)n0 * K_IN;

    // Per-thread cp.async source/dest precompute
    // A: 512 chunks of 16B (128 rows x 4 chunks); 2 per thread.
    // B: 1024 chunks (256 rows x 4); 4 per thread.
    int  a_row[2], a_ch[2];
    uint32_t a_so[2];
    #pragma unroll
    for (int i = 0; i < 2; i++) {
        int ca = tid + i * 256;
        a_row[i] = ca >> 2; a_ch[i] = ca & 3;
        a_so[i] = swz64(a_row[i], a_ch[i]);
    }
    int  b_row[4], b_ch[4];
    uint32_t b_so[4];
    #pragma unroll
    for (int i = 0; i < 4; i++) {
        int cb = tid + i * 256;
        b_row[i] = cb >> 2; b_ch[i] = cb & 3;
        b_so[i] = swz64(b_row[i], b_ch[i]);
    }

    auto load_stage = [&](int kt, int s) {
        const uint32_t sA = sb + (uint32_t)s * STAGE_BYTES;
        const uint32_t sB = sA + A_TILE;
        const size_t ko = (size_t)kt * BK;
        #pragma unroll
        for (int i = 0; i < 2; i++)
            CP_ASYNC16(sA + a_so[i], gA + (size_t)a_row[i] * K_IN + ko + a_ch[i] * 16);
        #pragma unroll
        for (int i = 0; i < 4; i++)
            CP_ASYNC16(sB + b_so[i], gB + (size_t)b_row[i] * K_IN + ko + b_ch[i] * 16);
        CP_COMMIT();
    };

    // Warp tiling: warp grid 2 (M) x 4 (N); warp tile 64x64
    const int warpM = (wid & 1) * 64;
    const int warpN = (wid >> 1) * 64;

    int acc[4][8][4];
    #pragma unroll
    for (int mt = 0; mt < 4; mt++)
        #pragma unroll
        for (int nt = 0; nt < 8; nt++)
            #pragma unroll
            for (int j = 0; j < 4; j++) acc[mt][nt][j] = 0;

    // ldmatrix lane address components.
    // A x4: matrices (m0-7/k0-15, m8-15/k0-15, m0-7/k16-31, m8-15/k16-31)
    //   row = warpM + mt*16 + (lane&15), chunk-half = lane>>4
    const int a_lrow = warpM + (lane & 15);       // + mt*16
    const int a_lhalf = lane >> 4;                // 0: k0-15, 1: k16-31
    // B x4: two n-tiles per load: lanes0-7 (nt0,k0) 8-15 (nt0,k16)
    //       16-23 (nt1,k0) 24-31 (nt1,k16)
    const int b_g2    = lane >> 3;                // 0..3
    const int b_lrow  = warpN + ((b_g2 >> 1) * 8) + (lane & 7);  // + ntp*16
    const int b_lhalf = b_g2 & 1;

    // ---------------- prologue: fill STAGES-1 stages ----------------
    #pragma unroll
    for (int s = 0; s < STAGES - 1; s++) load_stage(s, s);

    // ---------------- mainloop ----------------
    for (int kt = 0; kt < NKT; kt++) {
        CP_WAIT(STAGES - 2);
        __syncthreads();

        const int nk = kt + STAGES - 1;
        if (nk < NKT) load_stage(nk, nk & (STAGES - 1));
        else          CP_COMMIT();                 // keep group count aligned

        const uint32_t sA = sb + (uint32_t)(kt & (STAGES - 1)) * STAGE_BYTES;
        const uint32_t sB = sA + A_TILE;

        #pragma unroll
        for (int ks = 0; ks < 2; ks++) {           // two k32 steps per BK=64
            uint32_t afr[4][4];
            #pragma unroll
            for (int mt = 0; mt < 4; mt++) {
                const int r = a_lrow + mt * 16;
                ldmatrix_x4(afr[mt][0], afr[mt][1], afr[mt][2], afr[mt][3],
                            sA + swz64(r, ks * 2 + a_lhalf));
            }
            uint32_t bfr[8][2];
            #pragma unroll
            for (int ntp = 0; ntp < 4; ntp++) {
                const int r = b_lrow + ntp * 16;
                ldmatrix_x4(bfr[2 * ntp][0], bfr[2 * ntp][1],
                            bfr[2 * ntp + 1][0], bfr[2 * ntp + 1][1],
                            sB + swz64(r, ks * 2 + b_lhalf));
            }
            #pragma unroll
            for (int mt = 0; mt < 4; mt++)
                #pragma unroll
                for (int nt = 0; nt < 8; nt++)
                    mma_s8(acc[mt][nt], afr[mt], bfr[nt]);
        }
    }

    // ---------------- fused quantize epilogue ----------------
    const float sx = scale_ptr[0];
    const float scale = __fdiv_rn(__fmul_rn(sx, 0.1f), 0.1f);  // match ref op order
    const int g = lane >> 2, t4 = lane & 3;

    #pragma unroll
    for (int mt = 0; mt < 4; mt++) {
        const int mrow = m0 + warpM + mt * 16 + g;
        #pragma unroll
        for (int nt = 0; nt < 8; nt++) {
            const int n = n0 + warpN + nt * 8 + 2 * t4;
            int q[4];
            #pragma unroll
            for (int j = 0; j < 4; j++) {
                float yf = __fmul_rn((float)acc[mt][nt][j], scale);
                float rr = rintf(yf);                       // half-to-even == jnp.round
                rr = fminf(127.0f, fmaxf(-128.0f, rr));
                q[j] = (int)rr;
            }
            if (!FOUT) {
                int8_t* base = (int8_t*)outv;
                uint16_t p01 = (uint16_t)((q[0] & 0xFF) | ((q[1] & 0xFF) << 8));
                uint16_t p23 = (uint16_t)((q[2] & 0xFF) | ((q[3] & 0xFF) << 8));
                *reinterpret_cast<uint16_t*>(base + (size_t)mrow * N_OUT + n) = p01;
                *reinterpret_cast<uint16_t*>(base + (size_t)(mrow + 8) * N_OUT + n) = p23;
            } else {
                float* base = (float*)outv;
                *reinterpret_cast<float2*>(base + (size_t)mrow * N_OUT + n) =
                    make_float2((float)q[0], (float)q[1]);
                *reinterpret_cast<float2*>(base + (size_t)(mrow + 8) * N_OUT + n) =
                    make_float2((float)q[2], (float)q[3]);
            }
        }
    }
}

// ============================================================================
// Tail writers for the secondary output (OUT_SCALE = 0.1f), if present
// ============================================================================
__global__ void tail_scale_i8(int8_t* out) {
    if (threadIdx.x == 0)
        *reinterpret_cast<float*>(out + (size_t)MN) = 0.1f;
}
__global__ void tail_scale_f32(float* out) {
    if (threadIdx.x == 0)
        out[(size_t)MN] = 0.1f;
}

// ============================================================================
// Launch
// ============================================================================
extern "C" void kernel_launch(void* const* d_in, const int* in_sizes, int n_in,
                              void* d_out, int out_size) {
    const int*   x_q     = (const int*)d_in[0];   // [8192, 4096] int32 carriers
    const int*   w_q     = (const int*)d_in[1];   // [4096, 4096] int32 carriers
    const float* scale_x = (const float*)d_in[2];

    // Phase 1: pack int32 -> int8 scratch
    const size_t total_threads = XT + WT;         // 3145728
    pack_kernel<<<(unsigned)(total_threads / 256), 256>>>(x_q, w_q);

    // Phase 2: IMMA GEMM + fused quantize epilogue
    dim3 grid(N_OUT / BN, M_TOK / BM);            // (16, 64) = 1024 CTAs
    const bool fout = (out_size == (int)(MN + 1));

    if (fout) {
        cudaFuncSetAttribute(gemm_i8_kernel<true>,
                             cudaFuncAttributeMaxDynamicSharedMemorySize, SMEM_TOTAL);
        gemm_i8_kernel<true><<<grid, 256, SMEM_TOTAL>>>(scale_x, d_out);
        tail_scale_f32<<<1, 32>>>((float*)d_out);
    } else {
        cudaFuncSetAttribute(gemm_i8_kernel<false>,
                             cudaFuncAttributeMaxDynamicSharedMemorySize, SMEM_TOTAL);
        gemm_i8_kernel<false><<<grid, 256, SMEM_TOTAL>>>(scale_x, d_out);
        if ((long long)out_size >= MN + 4)        // int8 y + packed f32 scale tail
            tail_scale_i8<<<1, 32>>>((int8_t*)d_out);
    }
}

// round 6
// speedup vs baseline: 1.0031x; 1.0031x over previous
#include <cuda_runtime.h>
#include <cstdint>

// ============================================================================
// Problem constants
// ============================================================================
static constexpr int M_TOK = 8192;
static constexpr int N_OUT = 4096;
static constexpr int K_IN  = 4096;
static constexpr long long MN = (long long)M_TOK * N_OUT;   // 33554432

// GEMM tiling (baseline-PTX path: mma.sync m16n8k32 s8 + cp.async + ldmatrix)
static constexpr int BM = 128;
static constexpr int BN = 256;
static constexpr int BK = 64;                // bytes of K per stage (int8)
static constexpr int NKT = K_IN / BK;        // 64 iterations
static constexpr int STAGES = 4;

static constexpr int A_TILE = BM * BK;       // 8192 B
static constexpr int B_TILE = BN * BK;       // 16384 B
static constexpr int STAGE_BYTES = A_TILE + B_TILE;       // 24576 B
static constexpr int SMEM_TOTAL  = STAGES * STAGE_BYTES;  // 98304 B

static constexpr int NTHREADS = 512;         // 16 warps: warp grid 2(M) x 8(N)

// Packed int8 operand scratch (__device__ globals: allowed, no allocation)
__device__ __align__(1024) int8_t g_xq[(size_t)M_TOK * K_IN];   // 32 MB
__device__ __align__(1024) int8_t g_wq[(size_t)N_OUT * K_IN];   // 16 MB

// ============================================================================
// PTX helpers (ALL baseline-PTX — nothing 'sm_103a'-gated)
// ============================================================================
__device__ __forceinline__ uint32_t smem_u32(const void* p) {
    uint32_t a;
    asm("{ .reg .u64 t; cvta.to.shared.u64 t, %1; cvt.u32.u64 %0, t; }"
        : "=r"(a) : "l"(p));
    return a;
}

#define CP_ASYNC16(sdst, gsrc) \
    asm volatile("cp.async.cg.shared.global [%0], [%1], 16;" \
                 :: "r"(sdst), "l"(gsrc) : "memory")
#define CP_COMMIT() asm volatile("cp.async.commit_group;" ::: "memory")
#define CP_WAIT(n)  asm volatile("cp.async.wait_group %0;" :: "n"(n) : "memory")

// Swizzled byte offset inside a [rows][64B] tile: 4 chunks of 16B per row,
// chunk ^= (row>>1)&3  ->  conflict-free for both cp.async stores and
// ldmatrix 8-row reads (verified in R5: bit-exact pass).
__device__ __forceinline__ uint32_t swz64(int row, int ch) {
    return (uint32_t)(row * 64 + ((ch ^ ((row >> 1) & 3)) << 4));
}

__device__ __forceinline__ void ldmatrix_x4(uint32_t& r0, uint32_t& r1,
                                            uint32_t& r2, uint32_t& r3,
                                            uint32_t addr) {
    asm volatile("ldmatrix.sync.aligned.m8n8.x4.shared.b16 {%0,%1,%2,%3}, [%4];"
                 : "=r"(r0), "=r"(r1), "=r"(r2), "=r"(r3) : "r"(addr));
}

__device__ __forceinline__ void mma_s8(int* c, const uint32_t* a, const uint32_t* b) {
    asm volatile(
        "mma.sync.aligned.m16n8k32.row.col.s32.s8.s8.s32 "
        "{%0,%1,%2,%3}, {%4,%5,%6,%7}, {%8,%9}, {%0,%1,%2,%3};"
        : "+r"(c[0]), "+r"(c[1]), "+r"(c[2]), "+r"(c[3])
        : "r"(a[0]), "r"(a[1]), "r"(a[2]), "r"(a[3]), "r"(b[0]), "r"(b[1]));
}

// ============================================================================
// Kernel 1: int32 carriers -> packed int8 scratch (measured 36us, 81% DRAM)
// ============================================================================
static constexpr size_t XT = ((size_t)M_TOK * K_IN) / 16;   // 2097152
static constexpr size_t WT = ((size_t)N_OUT * K_IN) / 16;   // 1048576

__device__ __forceinline__ uint32_t pack4(int4 v) {
    return ((uint32_t)v.x & 0xFFu) | (((uint32_t)v.y & 0xFFu) << 8) |
           (((uint32_t)v.z & 0xFFu) << 16) | ((uint32_t)v.w << 24);
}

__global__ __launch_bounds__(256) void pack_kernel(const int* __restrict__ x,
                                                   const int* __restrict__ w) {
    size_t t = (size_t)blockIdx.x * 256 + threadIdx.x;
    const int4* src;
    int8_t* dst;
    if (t < XT) {
        src = reinterpret_cast<const int4*>(x) + t * 4;
        dst = g_xq + t * 16;
    } else {
        size_t u = t - XT;
        src = reinterpret_cast<const int4*>(w) + u * 4;
        dst = g_wq + u * 16;
    }
    int4 a = src[0], b = src[1], c = src[2], d = src[3];
    *reinterpret_cast<uint4*>(dst) =
        make_uint4(pack4(a), pack4(b), pack4(c), pack4(d));
}

// ============================================================================
// Kernel 2: multistage cp.async + ldmatrix + IMMA GEMM
//   512 threads, 16 warps, warp tile 64x32 (acc = 64 regs/thread, NO spill),
//   CTA tile 128x256, BK=64, 4 stages.
// ============================================================================
template <bool FOUT>
__global__ __launch_bounds__(NTHREADS, 1)
void gemm_i8_kernel(const float* __restrict__ scale_ptr, void* __restrict__ outv) {
    extern __shared__ char smem[];
    const uint32_t sb = smem_u32(smem);
    const int tid  = threadIdx.x;
    const int wid  = tid >> 5;
    const int lane = tid & 31;

    const int m0 = blockIdx.y * BM;
    const int n0 = blockIdx.x * BN;

    const int8_t* gA = g_xq + (size_t)m0 * K_IN;
    const int8_t* gB = g_wq + (size_t)n0 * K_IN;

    // Per-thread cp.async source/dest precompute (512 threads):
    // A: 512 chunks of 16B (128 rows x 4 chunks) -> 1 per thread.
    // B: 1024 chunks (256 rows x 4)              -> 2 per thread.
    const int a_row = tid >> 2, a_ch = tid & 3;
    const uint32_t a_so = swz64(a_row, a_ch);
    int b_row[2], b_ch[2];
    uint32_t b_so[2];
    #pragma unroll
    for (int i = 0; i < 2; i++) {
        int cb = tid + i * NTHREADS;
        b_row[i] = cb >> 2; b_ch[i] = cb & 3;
        b_so[i] = swz64(b_row[i], b_ch[i]);
    }

    auto load_stage = [&](int kt, int s) {
        const uint32_t sA = sb + (uint32_t)s * STAGE_BYTES;
        const uint32_t sB = sA + A_TILE;
        const size_t ko = (size_t)kt * BK;
        CP_ASYNC16(sA + a_so, gA + (size_t)a_row * K_IN + ko + a_ch * 16);
        #pragma unroll
        for (int i = 0; i < 2; i++)
            CP_ASYNC16(sB + b_so[i], gB + (size_t)b_row[i] * K_IN + ko + b_ch[i] * 16);
        CP_COMMIT();
    };

    // Warp tiling: warp grid 2 (M) x 8 (N); warp tile 64x32
    const int warpM = (wid & 1) * 64;
    const int warpN = (wid >> 1) * 32;

    int acc[4][4][4];
    #pragma unroll
    for (int mt = 0; mt < 4; mt++)
        #pragma unroll
        for (int nt = 0; nt < 4; nt++)
            #pragma unroll
            for (int j = 0; j < 4; j++) acc[mt][nt][j] = 0;

    // ldmatrix lane address components (identical mappings to the R5 pass).
    const int a_lrow  = warpM + (lane & 15);      // + mt*16
    const int a_lhalf = lane >> 4;                // 0: k0-15, 1: k16-31
    const int b_g2    = lane >> 3;                // 0..3
    const int b_lrow  = warpN + ((b_g2 >> 1) * 8) + (lane & 7);  // + ntp*16
    const int b_lhalf = b_g2 & 1;

    // ---------------- prologue: fill STAGES-1 stages ----------------
    #pragma unroll
    for (int s = 0; s < STAGES - 1; s++) load_stage(s, s);

    // ---------------- mainloop ----------------
    for (int kt = 0; kt < NKT; kt++) {
        CP_WAIT(STAGES - 2);
        __syncthreads();

        const int nk = kt + STAGES - 1;
        if (nk < NKT) load_stage(nk, nk & (STAGES - 1));
        else          CP_COMMIT();                 // keep group count aligned

        const uint32_t sA = sb + (uint32_t)(kt & (STAGES - 1)) * STAGE_BYTES;
        const uint32_t sB = sA + A_TILE;

        #pragma unroll
        for (int ks = 0; ks < 2; ks++) {           // two k32 steps per BK=64
            uint32_t afr[4][4];
            #pragma unroll
            for (int mt = 0; mt < 4; mt++) {
                const int r = a_lrow + mt * 16;
                ldmatrix_x4(afr[mt][0], afr[mt][1], afr[mt][2], afr[mt][3],
                            sA + swz64(r, ks * 2 + a_lhalf));
            }
            uint32_t bfr[4][2];
            #pragma unroll
            for (int ntp = 0; ntp < 2; ntp++) {
                const int r = b_lrow + ntp * 16;
                ldmatrix_x4(bfr[2 * ntp][0], bfr[2 * ntp][1],
                            bfr[2 * ntp + 1][0], bfr[2 * ntp + 1][1],
                            sB + swz64(r, ks * 2 + b_lhalf));
            }
            #pragma unroll
            for (int mt = 0; mt < 4; mt++)
                #pragma unroll
                for (int nt = 0; nt < 4; nt++)
                    mma_s8(acc[mt][nt], afr[mt], bfr[nt]);
        }
    }

    // ---------------- fused quantize epilogue ----------------
    const float sx = scale_ptr[0];
    const float scale = __fdiv_rn(__fmul_rn(sx, 0.1f), 0.1f);  // match ref op order
    const int g = lane >> 2, t4 = lane & 3;

    #pragma unroll
    for (int mt = 0; mt < 4; mt++) {
        const int mrow = m0 + warpM + mt * 16 + g;
        #pragma unroll
        for (int nt = 0; nt < 4; nt++) {
            const int n = n0 + warpN + nt * 8 + 2 * t4;
            int q[4];
            #pragma unroll
            for (int j = 0; j < 4; j++) {
                float yf = __fmul_rn((float)acc[mt][nt][j], scale);
                float rr = rintf(yf);                       // half-to-even == jnp.round
                rr = fminf(127.0f, fmaxf(-128.0f, rr));
                q[j] = (int)rr;
            }
            if (!FOUT) {
                int8_t* base = (int8_t*)outv;
                uint16_t p01 = (uint16_t)((q[0] & 0xFF) | ((q[1] & 0xFF) << 8));
                uint16_t p23 = (uint16_t)((q[2] & 0xFF) | ((q[3] & 0xFF) << 8));
                *reinterpret_cast<uint16_t*>(base + (size_t)mrow * N_OUT + n) = p01;
                *reinterpret_cast<uint16_t*>(base + (size_t)(mrow + 8) * N_OUT + n) = p23;
            } else {
                float* base = (float*)outv;
                *reinterpret_cast<float2*>(base + (size_t)mrow * N_OUT + n) =
                    make_float2((float)q[0], (float)q[1]);
                *reinterpret_cast<float2*>(base + (size_t)(mrow + 8) * N_OUT + n) =
                    make_float2((float)q[2], (float)q[3]);
            }
        }
    }
}

// ============================================================================
// Tail writers for the secondary output (OUT_SCALE = 0.1f), if present
// ============================================================================
__global__ void tail_scale_i8(int8_t* out) {
    if (threadIdx.x == 0)
        *reinterpret_cast<float*>(out + (size_t)MN) = 0.1f;
}
__global__ void tail_scale_f32(float* out) {
    if (threadIdx.x == 0)
        out[(size_t)MN] = 0.1f;
}

// ============================================================================
// Launch
// ============================================================================
extern "C" void kernel_launch(void* const* d_in, const int* in_sizes, int n_in,
                              void* d_out, int out_size) {
    const int*   x_q     = (const int*)d_in[0];   // [8192, 4096] int32 carriers
    const int*   w_q     = (const int*)d_in[1];   // [4096, 4096] int32 carriers
    const float* scale_x = (const float*)d_in[2];

    // Phase 1: pack int32 -> int8 scratch
    const size_t total_threads = XT + WT;         // 3145728
    pack_kernel<<<(unsigned)(total_threads / 256), 256>>>(x_q, w_q);

    // Phase 2: IMMA GEMM + fused quantize epilogue
    dim3 grid(N_OUT / BN, M_TOK / BM);            // (16, 64) = 1024 CTAs
    const bool fout = (out_size == (int)(MN + 1));

    if (fout) {
        cudaFuncSetAttribute(gemm_i8_kernel<true>,
                             cudaFuncAttributeMaxDynamicSharedMemorySize, SMEM_TOTAL);
        gemm_i8_kernel<true><<<grid, NTHREADS, SMEM_TOTAL>>>(scale_x, d_out);
        tail_scale_f32<<<1, 32>>>((float*)d_out);
    } else {
        cudaFuncSetAttribute(gemm_i8_kernel<false>,
                             cudaFuncAttributeMaxDynamicSharedMemorySize, SMEM_TOTAL);
        gemm_i8_kernel<false><<<grid, NTHREADS, SMEM_TOTAL>>>(scale_x, d_out);
        if ((long long)out_size >= MN + 4)        // int8 y + packed f32 scale tail
            tail_scale_i8<<<1, 32>>>((int8_t*)d_out);
    }
}

// round 10
// speedup vs baseline: 7.7552x; 7.7311x over previous
#include <cuda_runtime.h>
#include <cuda_bf16.h>
#include <cstdint>

// ============================================================================
// Problem constants
// ============================================================================
static constexpr int M_TOK = 8192;
static constexpr int N_OUT = 4096;
static constexpr int K_IN  = 4096;
static constexpr long long MN = (long long)M_TOK * N_OUT;   // 33554432

static constexpr int NT = 288;               // 9 warps: 8 loader/epilogue + 1 MMA

// CTA tile
static constexpr int BM = 256;
static constexpr int BN = 256;
static constexpr int BKE = 64;               // K elems per stage (bf16) = 128 B rows
static constexpr int NKT = K_IN / BKE;       // 64 k-tiles
static constexpr int STAGES = 3;

static constexpr int A_TILE = BM * 128;      // 32768 B (256 rows x 128 B)
static constexpr int B_TILE = BN * 128;      // 32768 B
static constexpr int STAGE_BYTES = A_TILE + B_TILE;            // 65536
static constexpr int SM_FULL  = 0;           // 3 mbarriers
static constexpr int SM_EMPTY = 64;          // 3 mbarriers
static constexpr int SM_DONE  = 128;
static constexpr int SM_TMEM  = 136;
static constexpr int SM_TILES = 1024;
static constexpr int SMEM_LAUNCH = SM_TILES + STAGES * STAGE_BYTES;  // 197632

// kind::f16 idesc (cg1): dtype=F32(1)<<4, atype=BF16(1)<<7, btype=BF16(1)<<10,
// N/8 << 17, M/16 << 24.  (Field layout verified against example 0x8080490.)
static constexpr uint32_t IDESC_BF16 =
    (1u << 4) | (1u << 7) | (1u << 10) | ((BN / 8u) << 17) | ((128u / 16u) << 24);

// Scratch (__device__ globals: allowed, no allocation)
__device__ __align__(1024) __nv_bfloat16 g_xb[(size_t)M_TOK * K_IN];  // 64 MB
__device__ __align__(1024) __nv_bfloat16 g_wb[(size_t)N_OUT * K_IN];  // 32 MB
__device__ __align__(1024) int8_t g_xq[(size_t)M_TOK * K_IN];         // fallback
__device__ __align__(1024) int8_t g_wq[(size_t)N_OUT * K_IN];         // fallback

// ============================================================================
// Common helpers
// ============================================================================
__device__ __forceinline__ uint32_t smem_u32(const void* p) {
    uint32_t a;
    asm("{ .reg .u64 t; cvta.to.shared.u64 t, %1; cvt.u32.u64 %0, t; }"
        : "=r"(a) : "l"(p));
    return a;
}

#define CP_ASYNC16(sdst, gsrc) \
    asm volatile("cp.async.cg.shared.global [%0], [%1], 16;" \
                 :: "r"(sdst), "l"(gsrc) : "memory")

#define MBAR_INIT(addr, cnt) \
    asm volatile("mbarrier.init.shared.b64 [%0], %1;" :: "r"(addr), "r"(cnt) : "memory")

#define MBAR_WAIT(addr, ph) do {                                              \
    asm volatile(                                                             \
        "{\n\t.reg .pred P;\n"                                               \
        "WL_%=:\n\t"                                                          \
        "mbarrier.try_wait.parity.acquire.cta.shared::cta.b64 P, [%0], %1, 0x989680;\n\t" \
        "@P bra WD_%=;\n\t"                                                   \
        "bra WL_%=;\n"                                                        \
        "WD_%=:\n\t}"                                                         \
        :: "r"(addr), "r"(ph) : "memory");                                    \
} while (0)

#define CP_ASYNC_BAR_ARRIVE(bar) \
    asm volatile("cp.async.mbarrier.arrive.noinc.shared.b64 [%0];" \
                 :: "r"(bar) : "memory")

#define SWZ128(o) ((o) ^ (((o) >> 3) & 0x70))

// Quantize one fp32-exact-integer accumulator (matches ref op order)
__device__ __forceinline__ int quantize_f(float accf, float scale) {
    float yf = __fmul_rn(accf, scale);
    float rr = rintf(yf);                        // half-to-even == jnp.round
    rr = fminf(127.0f, fmaxf(-128.0f, rr));
    return (int)rr;
}

// ============================================================================
// tcgen05 (sm_103a arch-accelerated pass only; R7 confirmed these compile)
// ============================================================================
#if defined(__CUDA_ARCH_FEAT_SM103_ALL) || defined(__CUDA_ARCH_FEAT_SM100_ALL) || defined(__CUDA_ARCH_FEAT_SM101_ALL)
#define HAS_TCGEN05 1

__device__ __forceinline__ uint32_t elect_one() {
    uint32_t pred;
    asm volatile(
        "{\n\t.reg .pred p;\n\telect.sync _|p, 0xFFFFFFFF;\n\t"
        "selp.b32 %0, 1, 0, p;\n\t}" : "=r"(pred));
    return pred;
}

#define FENCE_PROXY_ASYNC_CTA() \
    asm volatile("fence.proxy.async.shared::cta;" ::: "memory")
#define TCGEN05_ALLOC(sp, n) \
    asm volatile("tcgen05.alloc.cta_group::1.sync.aligned.shared::cta.b32 [%0], %1;" \
                 :: "r"(sp), "r"((uint32_t)(n)) : "memory")
#define TCGEN05_DEALLOC(t, n) \
    asm volatile("tcgen05.dealloc.cta_group::1.sync.aligned.b32 %0, %1;" \
                 :: "r"(t), "r"((uint32_t)(n)))
#define TCGEN05_RELINQ() \
    asm volatile("tcgen05.relinquish_alloc_permit.cta_group::1.sync.aligned;")
#define TCGEN05_COMMIT(bar) \
    asm volatile("tcgen05.commit.cta_group::1.mbarrier::arrive::one.shared::cluster.b64 [%0];" \
                 :: "r"(bar) : "memory")
#define TCGEN05_FENCE_AFTER() \
    asm volatile("tcgen05.fence::after_thread_sync;" ::: "memory")
#define TCGEN05_FENCE_BEFORE() \
    asm volatile("tcgen05.fence::before_thread_sync;" ::: "memory")
#define TCGEN05_WAIT_LD() \
    asm volatile("tcgen05.wait::ld.sync.aligned;" ::: "memory")

#define TCGEN05_LD_32X32B_X32(r, tmem_addr) \
    asm volatile( \
        "tcgen05.ld.sync.aligned.32x32b.x32.b32 " \
        "{%0, %1, %2, %3, %4, %5, %6, %7, " \
        " %8, %9, %10, %11, %12, %13, %14, %15, " \
        " %16, %17, %18, %19, %20, %21, %22, %23, " \
        " %24, %25, %26, %27, %28, %29, %30, %31}, [%32];" \
        : "=r"((r)[0]),  "=r"((r)[1]),  "=r"((r)[2]),  "=r"((r)[3]), \
          "=r"((r)[4]),  "=r"((r)[5]),  "=r"((r)[6]),  "=r"((r)[7]), \
          "=r"((r)[8]),  "=r"((r)[9]),  "=r"((r)[10]), "=r"((r)[11]), \
          "=r"((r)[12]), "=r"((r)[13]), "=r"((r)[14]), "=r"((r)[15]), \
          "=r"((r)[16]), "=r"((r)[17]), "=r"((r)[18]), "=r"((r)[19]), \
          "=r"((r)[20]), "=r"((r)[21]), "=r"((r)[22]), "=r"((r)[23]), \
          "=r"((r)[24]), "=r"((r)[25]), "=r"((r)[26]), "=r"((r)[27]), \
          "=r"((r)[28]), "=r"((r)[29]), "=r"((r)[30]), "=r"((r)[31]) \
        : "r"(tmem_addr))

// K-major SW128 descriptor: layout=2, version=1 (Blackwell), SBO=64, LBO=1
static constexpr uint64_t SMEM_DESC_BASE_SW128 =
    (uint64_t(2) << 61) | (uint64_t(1) << 46) | (uint64_t(64) << 32) | (uint64_t(1) << 16);
#define MAKE_SMEM_DESC(a) (SMEM_DESC_BASE_SW128 | ((uint64_t)((a) >> 4) & 0x3FFF))

__device__ __forceinline__ void mma_bf16_ss(uint32_t d_tmem, uint64_t a_desc,
                                            uint64_t b_desc, uint32_t idesc,
                                            uint32_t enable) {
    asm volatile(
        "{\n\t.reg .pred p;\n\t"
        "setp.ne.u32 p, %5, 0;\n\t"
        "tcgen05.mma.cta_group::1.kind::f16 [%0], %1, %2, %3, {%4, %4, %4, %4}, p;\n\t}"
        :: "r"(d_tmem), "l"(a_desc), "l"(b_desc), "r"(idesc), "r"(0u), "r"(enable)
        : "memory");
}
#endif

// ============================================================================
// Kernel 1: int32 carriers -> bf16 (tcgen05 build) / int8 (fallback build)
// ============================================================================
static constexpr size_t XT = ((size_t)M_TOK * K_IN) / 16;   // 2097152
static constexpr size_t WT = ((size_t)N_OUT * K_IN) / 16;   // 1048576

__device__ __forceinline__ uint32_t pk_bf2(int a, int b) {
    uint32_t lo = (uint32_t)__bfloat16_as_ushort(__float2bfloat16_rn((float)a));
    uint32_t hi = (uint32_t)__bfloat16_as_ushort(__float2bfloat16_rn((float)b));
    return lo | (hi << 16);
}
__device__ __forceinline__ uint32_t pk_i8(int4 v) {
    return ((uint32_t)v.x & 0xFFu) | (((uint32_t)v.y & 0xFFu) << 8) |
           (((uint32_t)v.z & 0xFFu) << 16) | ((uint32_t)v.w << 24);
}

__global__ __launch_bounds__(256) void pack_kernel(const int* __restrict__ x,
                                                   const int* __restrict__ w) {
    size_t t = (size_t)blockIdx.x * 256 + threadIdx.x;
#if defined(HAS_TCGEN05)
    const int4* src;
    __nv_bfloat16* dst;
    if (t < XT) { src = reinterpret_cast<const int4*>(x) + t * 4; dst = g_xb + t * 16; }
    else { size_t u = t - XT; src = reinterpret_cast<const int4*>(w) + u * 4; dst = g_wb + u * 16; }
    int4 a = src[0], b = src[1], c = src[2], d = src[3];
    uint4 o0 = make_uint4(pk_bf2(a.x, a.y), pk_bf2(a.z, a.w),
                          pk_bf2(b.x, b.y), pk_bf2(b.z, b.w));
    uint4 o1 = make_uint4(pk_bf2(c.x, c.y), pk_bf2(c.z, c.w),
                          pk_bf2(d.x, d.y), pk_bf2(d.z, d.w));
    reinterpret_cast<uint4*>(dst)[0] = o0;
    reinterpret_cast<uint4*>(dst)[1] = o1;
#else
    const int4* src;
    int8_t* dst;
    if (t < XT) { src = reinterpret_cast<const int4*>(x) + t * 4; dst = g_xq + t * 16; }
    else { size_t u = t - XT; src = reinterpret_cast<const int4*>(w) + u * 4; dst = g_wq + u * 16; }
    int4 a = src[0], b = src[1], c = src[2], d = src[3];
    *reinterpret_cast<uint4*>(dst) =
        make_uint4(pk_i8(a), pk_i8(b), pk_i8(c), pk_i8(d));
#endif
}

// ============================================================================
// Kernel 2: tcgen05 bf16 GEMM (exact int math in fp32 accumulators)
//   CTA 256x256, BK=64 bf16, 3-stage cp.async->mbarrier pipeline,
//   warps 0-7: loaders then epilogue (TMEM->gmem); warp 8: MMA issuer.
//   TMEM: D0 cols 0-255 (rows 0-127), D1 cols 256-511 (rows 128-255).
// ============================================================================
template <bool FOUT>
__global__ __launch_bounds__(NT, 1)
void gemm_bf16_kernel(const float* __restrict__ scale_ptr, void* __restrict__ outv) {
    extern __shared__ char smem[];
    const uint32_t sb = smem_u32(smem);
    const int tid  = threadIdx.x;
    const int wid  = tid >> 5;
    const int lane = tid & 31;

    const int m0 = blockIdx.y * BM;
    const int n0 = blockIdx.x * BN;

#if defined(HAS_TCGEN05)
    if (tid == 0) {
        #pragma unroll
        for (int s = 0; s < STAGES; s++) {
            MBAR_INIT(sb + SM_FULL + 8 * s, 256);  // 256 loader-thread arrivals
            MBAR_INIT(sb + SM_EMPTY + 8 * s, 1);   // 1 tcgen05.commit arrival
        }
        MBAR_INIT(sb + SM_DONE, 1);
    }
    if (wid == 8) TCGEN05_ALLOC(sb + SM_TMEM, 512);  // full TMEM: 512 f32 cols
    __syncthreads();

    uint32_t tmem;
    asm volatile("ld.shared.b32 %0, [%1];" : "=r"(tmem) : "r"(sb + SM_TMEM));

    if (wid < 8) {
        // ---- loaders: 256 threads, 16 cp.async each per 64 kB stage ----
        const int ch = tid & 7;                  // 16B chunk within 128B row
        const int r0 = tid >> 3;                 // 0..31; rows r0 + 32*j
        const char* gAb = (const char*)g_xb + (size_t)(m0 + r0) * (K_IN * 2) + ch * 16;
        const char* gBb = (const char*)g_wb + (size_t)(n0 + r0) * (K_IN * 2) + ch * 16;
        uint32_t swz[8];
        #pragma unroll
        for (int j = 0; j < 8; j++)
            swz[j] = SWZ128((uint32_t)((r0 + 32 * j) * 128 + ch * 16));

        int es = 0, eph = 0, fs = 0;
        for (int kt = 0; kt < NKT; kt++) {
            if (kt >= STAGES) {
                MBAR_WAIT(sb + SM_EMPTY + 8 * es, eph);
                if (++es == STAGES) { es = 0; eph ^= 1; }
            }
            const uint32_t sA = sb + SM_TILES + fs * STAGE_BYTES;
            const uint32_t sB = sA + A_TILE;
            const size_t ko = (size_t)kt * 128;  // 64 bf16 = 128 B
            #pragma unroll
            for (int j = 0; j < 8; j++)
                CP_ASYNC16(sA + swz[j], gAb + (size_t)j * (32 * K_IN * 2) + ko);
            #pragma unroll
            for (int j = 0; j < 8; j++)
                CP_ASYNC16(sB + swz[j], gBb + (size_t)j * (32 * K_IN * 2) + ko);
            CP_ASYNC_BAR_ARRIVE(sb + SM_FULL + 8 * fs);
            if (++fs == STAGES) fs = 0;
        }
    } else {
        // ---- MMA issuer (single elected thread of warp 8) ----
        if (elect_one()) {
            int s = 0, ph = 0;
            for (int kt = 0; kt < NKT; kt++) {
                MBAR_WAIT(sb + SM_FULL + 8 * s, ph);
                FENCE_PROXY_ASYNC_CTA();
                const uint32_t sA = sb + SM_TILES + s * STAGE_BYTES;
                const uint64_t dA0 = MAKE_SMEM_DESC(sA);
                const uint64_t dA1 = MAKE_SMEM_DESC(sA + A_TILE / 2);  // rows 128-255
                const uint64_t dB  = MAKE_SMEM_DESC(sA + A_TILE);
                #pragma unroll
                for (int k = 0; k < 4; k++) {    // 4 x K=16 bf16 steps per stage
                    const uint32_t en = (uint32_t)((kt | k) != 0);
                    mma_bf16_ss(tmem,       dA0 + 2 * k, dB + 2 * k, IDESC_BF16, en);
                    mma_bf16_ss(tmem + 256, dA1 + 2 * k, dB + 2 * k, IDESC_BF16, en);
                }
                TCGEN05_COMMIT(sb + SM_EMPTY + 8 * s);
                if (++s == STAGES) { s = 0; ph ^= 1; }
            }
            TCGEN05_COMMIT(sb + SM_DONE);
        }
    }

    // ---- epilogue: warps 0-3 read D0 (rows 0-127), warps 4-7 read D1 ----
    if (wid < 8) {
        MBAR_WAIT(sb + SM_DONE, 0);
        TCGEN05_FENCE_AFTER();

        const float sx = scale_ptr[0];
        const float scale = __fdiv_rn(__fmul_rn(sx, 0.1f), 0.1f);
        const int half = wid >> 2;
        const int m = m0 + half * 128 + (wid & 3) * 32 + lane;
        const uint32_t tb = tmem + half * 256;

        #pragma unroll
        for (int cb = 0; cb < BN; cb += 32) {
            uint32_t r[32];
            TCGEN05_LD_32X32B_X32(r, tb + cb);
            TCGEN05_WAIT_LD();

            if (!FOUT) {
                uint32_t wpk[8];
                #pragma unroll
                for (int i = 0; i < 8; i++) {
                    uint32_t bits = 0;
                    #pragma unroll
                    for (int j = 0; j < 4; j++) {
                        const int qi = quantize_f(__uint_as_float(r[4 * i + j]), scale);
                        bits |= ((uint32_t)(qi & 0xFF)) << (8 * j);
                    }
                    wpk[i] = bits;
                }
                int8_t* op = (int8_t*)outv + (size_t)m * N_OUT + n0 + cb;
                reinterpret_cast<uint4*>(op)[0] = make_uint4(wpk[0], wpk[1], wpk[2], wpk[3]);
                reinterpret_cast<uint4*>(op)[1] = make_uint4(wpk[4], wpk[5], wpk[6], wpk[7]);
            } else {
                float* op = (float*)outv + (size_t)m * N_OUT + n0 + cb;
                #pragma unroll
                for (int i = 0; i < 8; i++) {
                    float4 v;
                    float* vv = &v.x;
                    #pragma unroll
                    for (int j = 0; j < 4; j++)
                        vv[j] = (float)quantize_f(__uint_as_float(r[4 * i + j]), scale);
                    reinterpret_cast<float4*>(op)[i] = v;
                }
            }
        }
        TCGEN05_FENCE_BEFORE();
    }

    __syncthreads();
    if (wid == 8) {
        TCGEN05_RELINQ();
        TCGEN05_DEALLOC(tmem, 512);
    }

#else
    // ---- compile-only fallback (never runs: sm_103a cubin exists) ----
    (void)smem;
    const float sx = scale_ptr[0];
    const float scale = __fdiv_rn(__fmul_rn(sx, 0.1f), 0.1f);
    for (int idx = tid; idx < BM * BN; idx += NT) {
        const int mm = idx >> 8, nn = idx & 255;
        const int* ax = (const int*)(g_xq + (size_t)(m0 + mm) * K_IN);
        const int* bw = (const int*)(g_wq + (size_t)(n0 + nn) * K_IN);
        int acc = 0;
        for (int k = 0; k < K_IN / 4; k++) acc = __dp4a(ax[k], bw[k], acc);
        const int q = quantize_f((float)acc, scale);
        if (!FOUT) ((int8_t*)outv)[(size_t)(m0 + mm) * N_OUT + n0 + nn] = (int8_t)q;
        else       ((float*)outv)[(size_t)(m0 + mm) * N_OUT + n0 + nn] = (float)q;
    }
#endif
}

// ============================================================================
// Tail writers for the secondary output (OUT_SCALE = 0.1f), if present
// ============================================================================
__global__ void tail_scale_i8(int8_t* out) {
    if (threadIdx.x == 0)
        *reinterpret_cast<float*>(out + (size_t)MN) = 0.1f;
}
__global__ void tail_scale_f32(float* out) {
    if (threadIdx.x == 0)
        out[(size_t)MN] = 0.1f;
}

// ============================================================================
// Launch
// ============================================================================
extern "C" void kernel_launch(void* const* d_in, const int* in_sizes, int n_in,
                              void* d_out, int out_size) {
    const int*   x_q     = (const int*)d_in[0];   // [8192, 4096] int32 carriers
    const int*   w_q     = (const int*)d_in[1];   // [4096, 4096] int32 carriers
    const float* scale_x = (const float*)d_in[2];

    // Phase 1: carriers -> bf16 scratch
    const size_t total_threads = XT + WT;         // 3145728
    pack_kernel<<<(unsigned)(total_threads / 256), 256>>>(x_q, w_q);

    // Phase 2: tcgen05 bf16 GEMM + fused quantize epilogue
    dim3 grid(N_OUT / BN, M_TOK / BM);            // (16, 32) = 512 CTAs
    const bool fout = (out_size == (int)(MN + 1));

    if (fout) {
        cudaFuncSetAttribute(gemm_bf16_kernel<true>,
                             cudaFuncAttributeMaxDynamicSharedMemorySize, SMEM_LAUNCH);
        gemm_bf16_kernel<true><<<grid, NT, SMEM_LAUNCH>>>(scale_x, d_out);
        tail_scale_f32<<<1, 32>>>((float*)d_out);
    } else {
        cudaFuncSetAttribute(gemm_bf16_kernel<false>,
                             cudaFuncAttributeMaxDynamicSharedMemorySize, SMEM_LAUNCH);
        gemm_bf16_kernel<false><<<grid, NT, SMEM_LAUNCH>>>(scale_x, d_out);
        if ((long long)out_size >= MN + 4)        // int8 y + packed f32 scale tail
            tail_scale_i8<<<1, 32>>>((int8_t*)d_out);
    }
}

// round 11
// speedup vs baseline: 7.9887x; 1.0301x over previous
#include <cuda_runtime.h>
#include <cuda_bf16.h>
#include <cstdint>

// ============================================================================
// Problem constants
// ============================================================================
static constexpr int M_TOK = 8192;
static constexpr int N_OUT = 4096;
static constexpr int K_IN  = 4096;
static constexpr long long MN = (long long)M_TOK * N_OUT;   // 33554432

static constexpr int NT = 320;       // 10 warps: 0-7 epilogue, 8 MMA, 9 bulk loader

// CTA tile
static constexpr int BM = 256;
static constexpr int BN = 256;
static constexpr int BKE = 64;               // K elems per stage (bf16) = 128 B rows
static constexpr int NKT = K_IN / BKE;       // 64 k-tiles
static constexpr int STAGES = 3;

static constexpr int A_TILE = BM * 128;      // 32768 B (256 rows x 128 B, pre-swizzled)
static constexpr int B_TILE = BN * 128;      // 32768 B
static constexpr int STAGE_BYTES = A_TILE + B_TILE;            // 65536
static constexpr int SM_FULL  = 0;           // 3 mbarriers
static constexpr int SM_EMPTY = 64;          // 3 mbarriers
static constexpr int SM_DONE  = 128;
static constexpr int SM_TMEM  = 136;
static constexpr int SM_TILES = 1024;
static constexpr int SMEM_LAUNCH = SM_TILES + STAGES * STAGE_BYTES;  // 197632

// kind::f16 idesc (cg1): dtype=F32(1)<<4, atype=BF16(1)<<7, btype=BF16(1)<<10,
// N/8 << 17, M/16 << 24.  (Verified: this layout reproduces example 0x8080490.)
static constexpr uint32_t IDESC_BF16 =
    (1u << 4) | (1u << 7) | (1u << 10) | ((BN / 8u) << 17) | ((128u / 16u) << 24);

// Tiled + pre-swizzled bf16 scratch:
//   g_xb: [mt 0..31][kt 0..63][32768 B tile], tile = 256 rows x 128 B,
//         within-tile offset = (row*128 + ch*16) ^ ((row&7)<<4)   (SW128)
//   g_wb: [nt 0..15][kt 0..63][32768 B tile], same layout.
__device__ __align__(1024) __nv_bfloat16 g_xb[(size_t)M_TOK * K_IN];  // 64 MB
__device__ __align__(1024) __nv_bfloat16 g_wb[(size_t)N_OUT * K_IN];  // 32 MB
__device__ __align__(1024) int8_t g_xq[(size_t)M_TOK * K_IN];         // fallback
__device__ __align__(1024) int8_t g_wq[(size_t)N_OUT * K_IN];         // fallback

// ============================================================================
// Common helpers
// ============================================================================
__device__ __forceinline__ uint32_t smem_u32(const void* p) {
    uint32_t a;
    asm("{ .reg .u64 t; cvta.to.shared.u64 t, %1; cvt.u32.u64 %0, t; }"
        : "=r"(a) : "l"(p));
    return a;
}

#define MBAR_INIT(addr, cnt) \
    asm volatile("mbarrier.init.shared.b64 [%0], %1;" :: "r"(addr), "r"(cnt) : "memory")

#define MBAR_WAIT(addr, ph) do {                                              \
    asm volatile(                                                             \
        "{\n\t.reg .pred P;\n"                                               \
        "WL_%=:\n\t"                                                          \
        "mbarrier.try_wait.parity.acquire.cta.shared::cta.b64 P, [%0], %1, 0x989680;\n\t" \
        "@P bra WD_%=;\n\t"                                                   \
        "bra WL_%=;\n"                                                        \
        "WD_%=:\n\t}"                                                         \
        :: "r"(addr), "r"(ph) : "memory");                                    \
} while (0)

#define MBAR_EXPECT_TX(addr, bytes) \
    asm volatile("mbarrier.arrive.expect_tx.shared.b64 _, [%0], %1;" \
                 :: "r"(addr), "r"((uint32_t)(bytes)) : "memory")

// Within-tile SW128 offset for (row, 16B-chunk ch): stays inside the 128B row.
__device__ __forceinline__ uint32_t tswz(int row, int ch) {
    return (uint32_t)((row * 128 + ch * 16) ^ ((row & 7) << 4));
}

// Quantize one fp32-exact-integer accumulator (matches ref op order)
__device__ __forceinline__ int quantize_f(float accf, float scale) {
    float yf = __fmul_rn(accf, scale);
    float rr = rintf(yf);                        // half-to-even == jnp.round
    rr = fminf(127.0f, fmaxf(-128.0f, rr));
    return (int)rr;
}

// ============================================================================
// tcgen05 + bulk-async (sm_103a arch-accelerated pass only)
// ============================================================================
#if defined(__CUDA_ARCH_FEAT_SM103_ALL) || defined(__CUDA_ARCH_FEAT_SM100_ALL) || defined(__CUDA_ARCH_FEAT_SM101_ALL)
#define HAS_TCGEN05 1

__device__ __forceinline__ uint32_t elect_one() {
    uint32_t pred;
    asm volatile(
        "{\n\t.reg .pred p;\n\telect.sync _|p, 0xFFFFFFFF;\n\t"
        "selp.b32 %0, 1, 0, p;\n\t}" : "=r"(pred));
    return pred;
}

// Non-tensor bulk copy global->shared with mbarrier tx-completion.
#define CP_BULK_G2S(sdst, gsrc, bytes, mbar) \
    asm volatile("cp.async.bulk.shared::cluster.global.mbarrier::complete_tx::bytes " \
                 "[%0], [%1], %2, [%3];" \
                 :: "r"(sdst), "l"(gsrc), "r"((uint32_t)(bytes)), "r"(mbar) : "memory")

#define TCGEN05_ALLOC(sp, n) \
    asm volatile("tcgen05.alloc.cta_group::1.sync.aligned.shared::cta.b32 [%0], %1;" \
                 :: "r"(sp), "r"((uint32_t)(n)) : "memory")
#define TCGEN05_DEALLOC(t, n) \
    asm volatile("tcgen05.dealloc.cta_group::1.sync.aligned.b32 %0, %1;" \
                 :: "r"(t), "r"((uint32_t)(n)))
#define TCGEN05_RELINQ() \
    asm volatile("tcgen05.relinquish_alloc_permit.cta_group::1.sync.aligned;")
#define TCGEN05_COMMIT(bar) \
    asm volatile("tcgen05.commit.cta_group::1.mbarrier::arrive::one.shared::cluster.b64 [%0];" \
                 :: "r"(bar) : "memory")
#define TCGEN05_FENCE_AFTER() \
    asm volatile("tcgen05.fence::after_thread_sync;" ::: "memory")
#define TCGEN05_FENCE_BEFORE() \
    asm volatile("tcgen05.fence::before_thread_sync;" ::: "memory")
#define TCGEN05_WAIT_LD() \
    asm volatile("tcgen05.wait::ld.sync.aligned;" ::: "memory")

#define TCGEN05_LD_32X32B_X32(r, tmem_addr) \
    asm volatile( \
        "tcgen05.ld.sync.aligned.32x32b.x32.b32 " \
        "{%0, %1, %2, %3, %4, %5, %6, %7, " \
        " %8, %9, %10, %11, %12, %13, %14, %15, " \
        " %16, %17, %18, %19, %20, %21, %22, %23, " \
        " %24, %25, %26, %27, %28, %29, %30, %31}, [%32];" \
        : "=r"((r)[0]),  "=r"((r)[1]),  "=r"((r)[2]),  "=r"((r)[3]), \
          "=r"((r)[4]),  "=r"((r)[5]),  "=r"((r)[6]),  "=r"((r)[7]), \
          "=r"((r)[8]),  "=r"((r)[9]),  "=r"((r)[10]), "=r"((r)[11]), \
          "=r"((r)[12]), "=r"((r)[13]), "=r"((r)[14]), "=r"((r)[15]), \
          "=r"((r)[16]), "=r"((r)[17]), "=r"((r)[18]), "=r"((r)[19]), \
          "=r"((r)[20]), "=r"((r)[21]), "=r"((r)[22]), "=r"((r)[23]), \
          "=r"((r)[24]), "=r"((r)[25]), "=r"((r)[26]), "=r"((r)[27]), \
          "=r"((r)[28]), "=r"((r)[29]), "=r"((r)[30]), "=r"((r)[31]) \
        : "r"(tmem_addr))

// K-major SW128 descriptor: layout=2, version=1 (Blackwell), SBO=64, LBO=1
static constexpr uint64_t SMEM_DESC_BASE_SW128 =
    (uint64_t(2) << 61) | (uint64_t(1) << 46) | (uint64_t(64) << 32) | (uint64_t(1) << 16);
#define MAKE_SMEM_DESC(a) (SMEM_DESC_BASE_SW128 | ((uint64_t)((a) >> 4) & 0x3FFF))

__device__ __forceinline__ void mma_bf16_ss(uint32_t d_tmem, uint64_t a_desc,
                                            uint64_t b_desc, uint32_t idesc,
                                            uint32_t enable) {
    asm volatile(
        "{\n\t.reg .pred p;\n\t"
        "setp.ne.u32 p, %5, 0;\n\t"
        "tcgen05.mma.cta_group::1.kind::f16 [%0], %1, %2, %3, {%4, %4, %4, %4}, p;\n\t}"
        :: "r"(d_tmem), "l"(a_desc), "l"(b_desc), "r"(idesc), "r"(0u), "r"(enable)
        : "memory");
}
#endif

// ============================================================================
// Kernel 1: int32 carriers -> tiled pre-swizzled bf16 scratch
//   One thread = one 16B chunk (8 elems). Warp writes 4 full 128B lines.
// ============================================================================
static constexpr size_t A_CH = ((size_t)M_TOK * K_IN) / 8;   // 4194304 chunks
static constexpr size_t B_CH = ((size_t)N_OUT * K_IN) / 8;   // 2097152 chunks

__device__ __forceinline__ uint32_t pk_bf2(int a, int b) {
    uint32_t lo = (uint32_t)__bfloat16_as_ushort(__float2bfloat16_rn((float)a));
    uint32_t hi = (uint32_t)__bfloat16_as_ushort(__float2bfloat16_rn((float)b));
    return lo | (hi << 16);
}
__device__ __forceinline__ uint32_t pk_i8(int4 v) {
    return ((uint32_t)v.x & 0xFFu) | (((uint32_t)v.y & 0xFFu) << 8) |
           (((uint32_t)v.z & 0xFFu) << 16) | ((uint32_t)v.w << 24);
}

__global__ __launch_bounds__(256) void pack_kernel(const int* __restrict__ x,
                                                   const int* __restrict__ w) {
    size_t t = (size_t)blockIdx.x * 256 + threadIdx.x;
#if defined(HAS_TCGEN05)
    const int4* src;
    char* base;
    int row, kt, ch, tidx;
    if (t < A_CH) {
        src = reinterpret_cast<const int4*>(x) + t * 2;
        const int kc = (int)(t & 511);           // chunk within row (4096/8)
        const int m  = (int)(t >> 9);
        kt = kc >> 3; ch = kc & 7;
        row = m & 255;
        tidx = (m >> 8) * 64 + kt;               // [mt][kt]
        base = (char*)g_xb;
    } else {
        size_t u = t - A_CH;
        src = reinterpret_cast<const int4*>(w) + u * 2;
        const int kc = (int)(u & 511);
        const int n  = (int)(u >> 9);
        kt = kc >> 3; ch = kc & 7;
        row = n & 255;
        tidx = (n >> 8) * 64 + kt;               // [nt][kt]
        base = (char*)g_wb;
    }
    int4 a = src[0], b = src[1];
    uint4 o = make_uint4(pk_bf2(a.x, a.y), pk_bf2(a.z, a.w),
                         pk_bf2(b.x, b.y), pk_bf2(b.z, b.w));
    *reinterpret_cast<uint4*>(base + (size_t)tidx * 32768 + tswz(row, ch)) = o;
#else
    // fallback pack (linear int8)
    const int4* src;
    int8_t* dst;
    if (t < A_CH) { src = reinterpret_cast<const int4*>(x) + t * 2; dst = g_xq + t * 8; }
    else { size_t u = t - A_CH; src = reinterpret_cast<const int4*>(w) + u * 2; dst = g_wq + u * 8; }
    int4 a = src[0], b = src[1];
    *reinterpret_cast<uint2*>(dst) = make_uint2(pk_i8(a), pk_i8(b));
#endif
}

// ============================================================================
// Kernel 2: tcgen05 bf16 GEMM (exact int math in fp32 accumulators)
//   CTA 256x256, BK=64 bf16, 3-stage bulk-async pipeline:
//     warp 9:  single-thread cp.async.bulk issuer (2 x 32KB per k-tile)
//     warp 8:  MMA issuer (2 x M=128 kind::f16 per K=16 step)
//     warps 0-7: epilogue (TMEM -> quantize -> gmem)
// ============================================================================
template <bool FOUT>
__global__ __launch_bounds__(NT, 1)
void gemm_bf16_kernel(const float* __restrict__ scale_ptr, void* __restrict__ outv) {
    extern __shared__ char smem[];
    const uint32_t sb = smem_u32(smem);
    const int tid  = threadIdx.x;
    const int wid  = tid >> 5;
    const int lane = tid & 31;

    const int m0 = blockIdx.y * BM;
    const int n0 = blockIdx.x * BN;

#if defined(HAS_TCGEN05)
    if (tid == 0) {
        #pragma unroll
        for (int s = 0; s < STAGES; s++) {
            MBAR_INIT(sb + SM_FULL + 8 * s, 1);    // 1 expect_tx arrival + tx bytes
            MBAR_INIT(sb + SM_EMPTY + 8 * s, 1);   // 1 tcgen05.commit arrival
        }
        MBAR_INIT(sb + SM_DONE, 1);
    }
    if (wid == 8) TCGEN05_ALLOC(sb + SM_TMEM, 512);  // full TMEM: 512 f32 cols
    __syncthreads();

    uint32_t tmem;
    asm volatile("ld.shared.b32 %0, [%1];" : "=r"(tmem) : "r"(sb + SM_TMEM));

    if (wid == 9) {
        // ---- bulk loader: one thread, 2 x 32KB cp.async.bulk per k-tile ----
        if (lane == 0) {
            const char* gA = (const char*)g_xb + (size_t)blockIdx.y * (NKT * 32768);
            const char* gB = (const char*)g_wb + (size_t)blockIdx.x * (NKT * 32768);
            int es = 0, eph = 0, fs = 0;
            for (int kt = 0; kt < NKT; kt++) {
                if (kt >= STAGES) {
                    MBAR_WAIT(sb + SM_EMPTY + 8 * es, eph);
                    if (++es == STAGES) { es = 0; eph ^= 1; }
                }
                const uint32_t sA = sb + SM_TILES + fs * STAGE_BYTES;
                const uint32_t fb = sb + SM_FULL + 8 * fs;
                MBAR_EXPECT_TX(fb, STAGE_BYTES);
                CP_BULK_G2S(sA,          gA + (size_t)kt * 32768, A_TILE, fb);
                CP_BULK_G2S(sA + A_TILE, gB + (size_t)kt * 32768, B_TILE, fb);
                if (++fs == STAGES) fs = 0;
            }
        }
    } else if (wid == 8) {
        // ---- MMA issuer (single elected thread) ----
        if (elect_one()) {
            int s = 0, ph = 0;
            for (int kt = 0; kt < NKT; kt++) {
                MBAR_WAIT(sb + SM_FULL + 8 * s, ph);
                const uint32_t sA = sb + SM_TILES + s * STAGE_BYTES;
                const uint64_t dA0 = MAKE_SMEM_DESC(sA);
                const uint64_t dA1 = MAKE_SMEM_DESC(sA + A_TILE / 2);  // rows 128-255
                const uint64_t dB  = MAKE_SMEM_DESC(sA + A_TILE);
                #pragma unroll
                for (int k = 0; k < 4; k++) {    // 4 x K=16 bf16 steps per stage
                    const uint32_t en = (uint32_t)((kt | k) != 0);
                    mma_bf16_ss(tmem,       dA0 + 2 * k, dB + 2 * k, IDESC_BF16, en);
                    mma_bf16_ss(tmem + 256, dA1 + 2 * k, dB + 2 * k, IDESC_BF16, en);
                }
                TCGEN05_COMMIT(sb + SM_EMPTY + 8 * s);
                if (++s == STAGES) { s = 0; ph ^= 1; }
            }
            TCGEN05_COMMIT(sb + SM_DONE);
        }
    }

    // ---- epilogue: warps 0-3 read D0 (rows 0-127), warps 4-7 read D1 ----
    if (wid < 8) {
        MBAR_WAIT(sb + SM_DONE, 0);
        TCGEN05_FENCE_AFTER();

        const float sx = scale_ptr[0];
        const float scale = __fdiv_rn(__fmul_rn(sx, 0.1f), 0.1f);
        const int half = wid >> 2;
        const int m = m0 + half * 128 + (wid & 3) * 32 + lane;
        const uint32_t tb = tmem + half * 256;

        #pragma unroll
        for (int cb = 0; cb < BN; cb += 32) {
            uint32_t r[32];
            TCGEN05_LD_32X32B_X32(r, tb + cb);
            TCGEN05_WAIT_LD();

            if (!FOUT) {
                uint32_t wpk[8];
                #pragma unroll
                for (int i = 0; i < 8; i++) {
                    uint32_t bits = 0;
                    #pragma unroll
                    for (int j = 0; j < 4; j++) {
                        const int qi = quantize_f(__uint_as_float(r[4 * i + j]), scale);
                        bits |= ((uint32_t)(qi & 0xFF)) << (8 * j);
                    }
                    wpk[i] = bits;
                }
                int8_t* op = (int8_t*)outv + (size_t)m * N_OUT + n0 + cb;
                reinterpret_cast<uint4*>(op)[0] = make_uint4(wpk[0], wpk[1], wpk[2], wpk[3]);
                reinterpret_cast<uint4*>(op)[1] = make_uint4(wpk[4], wpk[5], wpk[6], wpk[7]);
            } else {
                float* op = (float*)outv + (size_t)m * N_OUT + n0 + cb;
                #pragma unroll
                for (int i = 0; i < 8; i++) {
                    float4 v;
                    float* vv = &v.x;
                    #pragma unroll
                    for (int j = 0; j < 4; j++)
                        vv[j] = (float)quantize_f(__uint_as_float(r[4 * i + j]), scale);
                    reinterpret_cast<float4*>(op)[i] = v;
                }
            }
        }
        TCGEN05_FENCE_BEFORE();
    }

    __syncthreads();
    if (wid == 8) {
        TCGEN05_RELINQ();
        TCGEN05_DEALLOC(tmem, 512);
    }

#else
    // ---- compile-only fallback (never runs: sm_103a cubin exists) ----
    (void)smem;
    const float sx = scale_ptr[0];
    const float scale = __fdiv_rn(__fmul_rn(sx, 0.1f), 0.1f);
    for (int idx = tid; idx < BM * BN; idx += NT) {
        const int mm = idx >> 8, nn = idx & 255;
        const int* ax = (const int*)(g_xq + (size_t)(m0 + mm) * K_IN);
        const int* bw = (const int*)(g_wq + (size_t)(n0 + nn) * K_IN);
        int acc = 0;
        for (int k = 0; k < K_IN / 4; k++) acc = __dp4a(ax[k], bw[k], acc);
        const int q = quantize_f((float)acc, scale);
        if (!FOUT) ((int8_t*)outv)[(size_t)(m0 + mm) * N_OUT + n0 + nn] = (int8_t)q;
        else       ((float*)outv)[(size_t)(m0 + mm) * N_OUT + n0 + nn] = (float)q;
    }
#endif
}

// ============================================================================
// Tail writers for the secondary output (OUT_SCALE = 0.1f), if present
// ============================================================================
__global__ void tail_scale_i8(int8_t* out) {
    if (threadIdx.x == 0)
        *reinterpret_cast<float*>(out + (size_t)MN) = 0.1f;
}
__global__ void tail_scale_f32(float* out) {
    if (threadIdx.x == 0)
        out[(size_t)MN] = 0.1f;
}

// ============================================================================
// Launch
// ============================================================================
extern "C" void kernel_launch(void* const* d_in, const int* in_sizes, int n_in,
                              void* d_out, int out_size) {
    const int*   x_q     = (const int*)d_in[0];   // [8192, 4096] int32 carriers
    const int*   w_q     = (const int*)d_in[1];   // [4096, 4096] int32 carriers
    const float* scale_x = (const float*)d_in[2];

    // Phase 1: carriers -> tiled pre-swizzled bf16 scratch
    const size_t total_threads = A_CH + B_CH;     // 6291456
    pack_kernel<<<(unsigned)(total_threads / 256), 256>>>(x_q, w_q);

    // Phase 2: tcgen05 bf16 GEMM + fused quantize epilogue
    dim3 grid(N_OUT / BN, M_TOK / BM);            // (16, 32) = 512 CTAs
    const bool fout = (out_size == (int)(MN + 1));

    if (fout) {
        cudaFuncSetAttribute(gemm_bf16_kernel<true>,
                             cudaFuncAttributeMaxDynamicSharedMemorySize, SMEM_LAUNCH);
        gemm_bf16_kernel<true><<<grid, NT, SMEM_LAUNCH>>>(scale_x, d_out);
        tail_scale_f32<<<1, 32>>>((float*)d_out);
    } else {
        cudaFuncSetAttribute(gemm_bf16_kernel<false>,
                             cudaFuncAttributeMaxDynamicSharedMemorySize, SMEM_LAUNCH);
        gemm_bf16_kernel<false><<<grid, NT, SMEM_LAUNCH>>>(scale_x, d_out);
        if ((long long)out_size >= MN + 4)        // int8 y + packed f32 scale tail
            tail_scale_i8<<<1, 32>>>((int8_t*)d_out);
    }
}